// round 1
// baseline (speedup 1.0000x reference)
#include <cuda_runtime.h>
#include <cuda_bf16.h>

// Problem constants
#define NB   8
#define NE   512
#define NL   8192
#define NLC  8188   // NL - (KS-1)
#define NKS  5

// Scratch (static __device__ — no runtime allocation)
__device__ float g_y[NB * NE * NL];   // conv output, zero-padded t in [NLC, NL)
__device__ float g_s[NB * NL];        // per-position scores

// ---------------------------------------------------------------------------
// Kernel 1: valid Conv1d(E->E, k=5) + bias, fp32, smem-tiled.
// CTA tile: 64 out-channels x 64 time steps, 256 threads, 4x4 micro-tile.
// ---------------------------------------------------------------------------
__global__ __launch_bounds__(256) void conv_kernel(
    const float* __restrict__ x,      // [B, E, L]
    const float* __restrict__ w,      // [E, E, 5]
    const float* __restrict__ bias) { // [E]
  const int TC = 16;
  __shared__ float xs[TC][72];          // x tile: [ci][t0..t0+67], padded stride
  __shared__ float ws[TC][NKS][68];     // w tile: [ci][k][e], padded stride

  const int t0 = blockIdx.x * 64;
  const int e0 = blockIdx.y * 64;
  const int b  = blockIdx.z;
  const int tid = threadIdx.x;
  const int tx = tid & 15;              // time group
  const int ty = tid >> 4;              // channel group

  float acc[4][4] = {};
  const float* xb = x + (b * NE) * NL;

  for (int cb = 0; cb < NE; cb += TC) {
    // --- load x tile: TC*68 = 1088 elements ---
    #pragma unroll
    for (int it = 0; it < 5; ++it) {
      int idx = tid + it * 256;
      if (idx < TC * 68) {
        int ci = idx / 68, j = idx - ci * 68;
        int t = t0 + j;
        xs[ci][j] = (t < NL) ? xb[(cb + ci) * NL + t] : 0.f;
      }
    }
    // --- load w tile: 64 e * (16 ci * 5 k) = 5120 elements ---
    // l -> e = l/80, r = l%80 (contiguous 80-float runs in gmem per e-row)
    #pragma unroll
    for (int it = 0; it < 20; ++it) {
      int l = tid + it * 256;
      int e = l / 80, r = l - e * 80;
      int ci = r / 5, k = r - ci * 5;
      ws[ci][k][e] = w[(e0 + e) * (NE * NKS) + (cb + ci) * NKS + k];
    }
    __syncthreads();

    // --- compute ---
    #pragma unroll
    for (int ci = 0; ci < TC; ++ci) {
      float xw[8];
      float4 xa = *reinterpret_cast<const float4*>(&xs[ci][tx * 4]);
      float4 xc = *reinterpret_cast<const float4*>(&xs[ci][tx * 4 + 4]);
      xw[0] = xa.x; xw[1] = xa.y; xw[2] = xa.z; xw[3] = xa.w;
      xw[4] = xc.x; xw[5] = xc.y; xw[6] = xc.z; xw[7] = xc.w;
      #pragma unroll
      for (int k = 0; k < NKS; ++k) {
        float4 wv = *reinterpret_cast<const float4*>(&ws[ci][k][ty * 4]);
        #pragma unroll
        for (int tt = 0; tt < 4; ++tt) {
          float xv = xw[tt + k];
          acc[0][tt] += wv.x * xv;
          acc[1][tt] += wv.y * xv;
          acc[2][tt] += wv.z * xv;
          acc[3][tt] += wv.w * xv;
        }
      }
    }
    __syncthreads();
  }

  // --- store (+bias); zero the tail t in [NLC, NL). NLC % 4 == 0 so each
  // float4 store is entirely valid or entirely padding. ---
  const int tbase = t0 + tx * 4;
  #pragma unroll
  for (int ee = 0; ee < 4; ++ee) {
    int e = e0 + ty * 4 + ee;
    float bv = bias[e];
    float4 v;
    if (tbase < NLC) {
      v.x = acc[ee][0] + bv; v.y = acc[ee][1] + bv;
      v.z = acc[ee][2] + bv; v.w = acc[ee][3] + bv;
    } else {
      v.x = 0.f; v.y = 0.f; v.z = 0.f; v.w = 0.f;
    }
    *reinterpret_cast<float4*>(&g_y[(b * NE + e) * NL + tbase]) = v;
  }
}

// ---------------------------------------------------------------------------
// Kernel 2: per-position scores s[b,t] = sum_e y[b,e,t] * score_w[e].
// (Scoring is linear, so a width-w block score is just the mean of s over
//  the block — no per-width einsum needed.)
// ---------------------------------------------------------------------------
__global__ __launch_bounds__(256) void score_kernel(const float* __restrict__ sw) {
  int t = blockIdx.x * 256 + threadIdx.x;
  int b = blockIdx.y;
  const float* yb = g_y + (b * NE) * NL + t;
  float acc = 0.f;
  #pragma unroll 8
  for (int e = 0; e < NE; ++e) {
    acc += yb[e * NL] * __ldg(&sw[e]);
  }
  g_s[b * NL + t] = acc;
}

// ---------------------------------------------------------------------------
// Kernel 3: fused candidate build + softmax over widths {1,2,3} + 2x avgpool.
// One thread per output element (b, e, to). t0 = 2*to, t1 = t0+1 share the
// same width-2 block. y/s tails are pre-zeroed, so only the w=3 t>=8190
// case needs an explicit guard.
// ---------------------------------------------------------------------------
__global__ __launch_bounds__(256) void out_kernel(float* __restrict__ out) {
  int idx = blockIdx.x * 256 + threadIdx.x;     // == (b*NE + e)*4096 + to
  int to = idx & 4095;
  int be = idx >> 12;                           // b*NE + e
  int b  = be >> 9;

  const float* y = g_y + be * NL;
  const float* s = g_s + b * NL;

  int t0 = to * 2;
  float s0 = s[t0], s1 = s[t0 + 1];
  float y0 = y[t0], y1 = y[t0 + 1];
  float sc2 = 0.5f * (s0 + s1);    // width-2 block = {t0, t1} for both halves
  float c2  = 0.5f * (y0 + y1);

  float r = 0.f;
  #pragma unroll
  for (int h = 0; h < 2; ++h) {
    int t = t0 + h;
    float sc1 = h ? s1 : s0;
    float c1  = h ? y1 : y0;
    float sc3, c3;
    if (t < 8190) {                // width-3 repeat length = 8190
      int base = (t / 3) * 3;
      sc3 = (s[base] + s[base + 1] + s[base + 2]) * (1.f / 3.f);
      c3  = (y[base] + y[base + 1] + y[base + 2]) * (1.f / 3.f);
    } else {
      sc3 = 0.f; c3 = 0.f;
    }
    float m  = fmaxf(sc1, fmaxf(sc2, sc3));
    float e1 = __expf(sc1 - m);
    float e2 = __expf(sc2 - m);
    float e3 = __expf(sc3 - m);
    float inv = 1.f / (e1 + e2 + e3);
    r += (e1 * c1 + e2 * c2 + e3 * c3) * inv;
  }
  out[idx] = 0.5f * r;   // 2x average-pool downsample
}

// ---------------------------------------------------------------------------
extern "C" void kernel_launch(void* const* d_in, const int* in_sizes, int n_in,
                              void* d_out, int out_size) {
  const float* x  = (const float*)d_in[0];  // [8,512,8192]
  const float* cw = (const float*)d_in[1];  // [512,512,5]
  const float* cb = (const float*)d_in[2];  // [512]
  const float* sw = (const float*)d_in[3];  // [512]
  float* out = (float*)d_out;               // [8,512,4096]

  dim3 gConv(NL / 64, NE / 64, NB);         // (128, 8, 8)
  conv_kernel<<<gConv, 256>>>(x, cw, cb);

  dim3 gScore(NL / 256, NB);                // (32, 8)
  score_kernel<<<gScore, 256>>>(sw);

  int total = NB * NE * (NL / 2);           // 16,777,216
  out_kernel<<<total / 256, 256>>>(out);
}

// round 4
// speedup vs baseline: 1.8755x; 1.8755x over previous
#include <cuda_runtime.h>
#include <cuda_bf16.h>
#include <cstdint>

#define NB  8
#define NE  512
#define NL  8192
#define NLC 8188
#define XL  8448            // NL + 256 pad rows (zeroed)

// ---- conv GEMM tiling (mma.sync path) ----
#define KCH   64                  // K elems per stage chunk
#define MAT_BYTES 16384           // 128 rows x 128B (one matrix, one stage)
#define STAGE_BYTES (4 * MAT_BYTES)   // Ah | Al | Bh | Bl
#define NSTAGE 3
#define SMEM_SZ (1024 + NSTAGE * STAGE_BYTES)
#define ITERS 40                  // 2560 / 64

// ---- scratch (__device__ globals; no runtime allocation) ----
__device__ __nv_bfloat16 g_xt_hi[(size_t)NB * XL * NE];
__device__ __nv_bfloat16 g_xt_lo[(size_t)NB * XL * NE];
__device__ __nv_bfloat16 g_wt_hi[NE * NE * 5];
__device__ __nv_bfloat16 g_wt_lo[NE * NE * 5];
__device__ float g_y[(size_t)NB * NE * NL];
__device__ float g_s[NB * NL];

// ---------------------------------------------------------------------------
__device__ __forceinline__ uint32_t swz(uint32_t o) { return o ^ ((o >> 3) & 0x70); }

__device__ __forceinline__ void cp16(uint32_t dst, const void* src) {
  asm volatile("cp.async.cg.shared.global [%0], [%1], 16;" :: "r"(dst), "l"(src));
}

__device__ __forceinline__ void ldsm4(uint32_t& r0, uint32_t& r1, uint32_t& r2,
                                      uint32_t& r3, uint32_t addr) {
  asm volatile("ldmatrix.sync.aligned.m8n8.x4.shared.b16 {%0,%1,%2,%3}, [%4];"
               : "=r"(r0), "=r"(r1), "=r"(r2), "=r"(r3) : "r"(addr));
}

__device__ __forceinline__ void mma16816(float* d, const uint32_t* a,
                                         uint32_t b0, uint32_t b1) {
  asm volatile(
    "mma.sync.aligned.m16n8k16.row.col.f32.bf16.bf16.f32 "
    "{%0,%1,%2,%3}, {%4,%5,%6,%7}, {%8,%9}, {%0,%1,%2,%3};"
    : "+f"(d[0]), "+f"(d[1]), "+f"(d[2]), "+f"(d[3])
    : "r"(a[0]), "r"(a[1]), "r"(a[2]), "r"(a[3]), "r"(b0), "r"(b1));
}

// ---------------------------------------------------------------------------
// prep_w: conv_w [E][E][5] fp32 -> wt_{hi,lo}[e][k*512+ci] bf16 split
// ---------------------------------------------------------------------------
__global__ __launch_bounds__(256) void prep_w(const float* __restrict__ w) {
  int idx = blockIdx.x * 256 + threadIdx.x;       // e*2560 + (k*512+ci)
  int e = idx / 2560, kk = idx - e * 2560;
  int k = kk >> 9, ci = kk & 511;
  float v = w[e * 2560 + ci * 5 + k];
  __nv_bfloat16 h = __float2bfloat16(v);
  g_wt_hi[idx] = h;
  g_wt_lo[idx] = __float2bfloat16(v - __bfloat162float(h));
}

// ---------------------------------------------------------------------------
// prep_x: x [B][E][L] fp32 -> xt_{hi,lo}[b][t][ci] bf16 split (transpose),
// rows t in [NL, XL) zeroed.
// ---------------------------------------------------------------------------
__global__ __launch_bounds__(256) void prep_x(const float* __restrict__ x) {
  __shared__ float tile[32][33];
  int t0 = blockIdx.x * 32;
  int c0 = blockIdx.y * 32;
  int b  = blockIdx.z;
  int tx = threadIdx.x & 31, ty = threadIdx.x >> 5;
  #pragma unroll
  for (int j = 0; j < 4; ++j) {
    int t = t0 + tx, c = c0 + ty + 8 * j;
    tile[ty + 8 * j][tx] = (t < NL) ? x[((size_t)b * NE + c) * NL + t] : 0.f;
  }
  __syncthreads();
  #pragma unroll
  for (int j = 0; j < 4; ++j) {
    int t = t0 + ty + 8 * j;
    float v = tile[tx][ty + 8 * j];
    __nv_bfloat16 h = __float2bfloat16(v);
    size_t off = ((size_t)b * XL + t) * NE + c0 + tx;
    g_xt_hi[off] = h;
    g_xt_lo[off] = __float2bfloat16(v - __bfloat162float(h));
  }
}

// ---------------------------------------------------------------------------
// conv_mma: y[e,t] = bias[e] + sum_{k,ci} W[e,ci,k]*x[ci,t+k]
// CTA 128x128, warps 2x4 (64x32 each), split-bf16 3-pass on mma.sync.
// 3-stage cp.async pipeline, SW128-swizzled smem.
// ---------------------------------------------------------------------------
__device__ __forceinline__ void load_stage(int i, uint32_t sb, int tid,
                                           int e0, int b, int t0) {
  int k  = i >> 3;
  int c0 = (i & 7) * KCH;
  const __nv_bfloat16* wh = g_wt_hi + (size_t)e0 * 2560 + k * 512 + c0;
  const __nv_bfloat16* wl = g_wt_lo + (size_t)e0 * 2560 + k * 512 + c0;
  const __nv_bfloat16* xh = g_xt_hi + ((size_t)b * XL + t0 + k) * NE + c0;
  const __nv_bfloat16* xl = g_xt_lo + ((size_t)b * XL + t0 + k) * NE + c0;
  #pragma unroll
  for (int j = 0; j < 4; ++j) {
    int q = tid + j * 256;          // 0..1023
    int r = q >> 3, ch = q & 7;     // row 0..127, 16B chunk 0..7
    uint32_t d = swz((uint32_t)(r * 128 + ch * 16));
    cp16(sb + 0 * MAT_BYTES + d, wh + (size_t)r * 2560 + ch * 8);
    cp16(sb + 1 * MAT_BYTES + d, wl + (size_t)r * 2560 + ch * 8);
    cp16(sb + 2 * MAT_BYTES + d, xh + (size_t)r * NE + ch * 8);
    cp16(sb + 3 * MAT_BYTES + d, xl + (size_t)r * NE + ch * 8);
  }
  asm volatile("cp.async.commit_group;" ::: "memory");
}

__global__ __launch_bounds__(256, 1) void conv_mma(const float* __restrict__ bias) {
  extern __shared__ char dsm[];
  uint32_t raw  = (uint32_t)__cvta_generic_to_shared(dsm);
  uint32_t base = (raw + 1023) & ~1023u;

  const int tid = threadIdx.x;
  const int mt = blockIdx.x & 3;
  const int tt = blockIdx.x >> 2;
  const int b  = blockIdx.y;
  const int e0 = mt * 128;
  const int t0 = tt * 128;

  const int l   = tid & 31;
  const int wrp = tid >> 5;
  const int m0w = (wrp >> 2) * 64;
  const int n0w = (wrp & 3) * 32;

  // per-lane ldmatrix row indices
  const int rA = (l & 15);                            // A: row within m16 tile
  const int cA = (l >> 4) * 16;                       // A: 16B chunk byte within k16
  const int rB = (l & 7) + ((l >> 4) & 1) * 8;        // B: row within n16 pair
  const int cB = ((l >> 3) & 1) * 16;                 // B: 16B chunk byte within k16

  float acc[4][4][4];
  #pragma unroll
  for (int i = 0; i < 4; ++i)
    #pragma unroll
    for (int j = 0; j < 4; ++j)
      #pragma unroll
      for (int q = 0; q < 4; ++q) acc[i][j][q] = 0.f;

  load_stage(0, base + 1024, tid, e0, b, t0);
  load_stage(1, base + 1024 + STAGE_BYTES, tid, e0, b, t0);

  for (int i = 0; i < ITERS; ++i) {
    if (i >= ITERS - 2) asm volatile("cp.async.wait_group 0;" ::: "memory");
    else                asm volatile("cp.async.wait_group 1;" ::: "memory");
    __syncthreads();
    if (i + 2 < ITERS)
      load_stage(i + 2, base + 1024 + (uint32_t)((i + 2) % NSTAGE) * STAGE_BYTES,
                 tid, e0, b, t0);

    uint32_t sb = base + 1024 + (uint32_t)(i % NSTAGE) * STAGE_BYTES;
    uint32_t sAh = sb, sAl = sb + MAT_BYTES, sBh = sb + 2 * MAT_BYTES,
             sBl = sb + 3 * MAT_BYTES;

    #pragma unroll
    for (int ks = 0; ks < 4; ++ks) {
      const int kb = ks * 32;   // byte offset of this k16 within 128B row
      uint32_t ah[4][4], al[4][4], bh[4][2], bl[4][2];
      #pragma unroll
      for (int mi = 0; mi < 4; ++mi) {
        uint32_t off = swz((uint32_t)((m0w + mi * 16 + rA) * 128 + kb + cA));
        ldsm4(ah[mi][0], ah[mi][1], ah[mi][2], ah[mi][3], sAh + off);
      }
      #pragma unroll
      for (int nj = 0; nj < 2; ++nj) {
        uint32_t off = swz((uint32_t)((n0w + nj * 16 + rB) * 128 + kb + cB));
        ldsm4(bh[nj * 2][0], bh[nj * 2][1], bh[nj * 2 + 1][0], bh[nj * 2 + 1][1],
              sBh + off);
      }
      #pragma unroll
      for (int mi = 0; mi < 4; ++mi)
        #pragma unroll
        for (int ni = 0; ni < 4; ++ni)
          mma16816(acc[mi][ni], ah[mi], bh[ni][0], bh[ni][1]);

      #pragma unroll
      for (int nj = 0; nj < 2; ++nj) {
        uint32_t off = swz((uint32_t)((n0w + nj * 16 + rB) * 128 + kb + cB));
        ldsm4(bl[nj * 2][0], bl[nj * 2][1], bl[nj * 2 + 1][0], bl[nj * 2 + 1][1],
              sBl + off);
      }
      #pragma unroll
      for (int mi = 0; mi < 4; ++mi)
        #pragma unroll
        for (int ni = 0; ni < 4; ++ni)
          mma16816(acc[mi][ni], ah[mi], bl[ni][0], bl[ni][1]);

      #pragma unroll
      for (int mi = 0; mi < 4; ++mi) {
        uint32_t off = swz((uint32_t)((m0w + mi * 16 + rA) * 128 + kb + cA));
        ldsm4(al[mi][0], al[mi][1], al[mi][2], al[mi][3], sAl + off);
      }
      #pragma unroll
      for (int mi = 0; mi < 4; ++mi)
        #pragma unroll
        for (int ni = 0; ni < 4; ++ni)
          mma16816(acc[mi][ni], al[mi], bh[ni][0], bh[ni][1]);
    }
  }

  // epilogue: d frag lane l -> rows m0+l/4 (+8), cols n0+2(l%4) (+1)
  #pragma unroll
  for (int mi = 0; mi < 4; ++mi) {
    #pragma unroll
    for (int half = 0; half < 2; ++half) {
      int e = e0 + m0w + mi * 16 + (l >> 2) + half * 8;
      float bv = bias[e];
      float* yrow = g_y + ((size_t)(b * NE + e)) * NL;
      #pragma unroll
      for (int ni = 0; ni < 4; ++ni) {
        int t = t0 + n0w + ni * 8 + 2 * (l & 3);
        float2 v;
        if (t < NLC) {
          v.x = acc[mi][ni][half * 2 + 0] + bv;
          v.y = acc[mi][ni][half * 2 + 1] + bv;
        } else { v.x = 0.f; v.y = 0.f; }
        *reinterpret_cast<float2*>(yrow + t) = v;
      }
    }
  }
}

// ---------------------------------------------------------------------------
// score: s[b,t] = sum_e y[b,e,t] * score_w[e]
// ---------------------------------------------------------------------------
__global__ __launch_bounds__(256) void score_kernel(const float* __restrict__ sw) {
  int t = blockIdx.x * 256 + threadIdx.x;
  int b = blockIdx.y;
  const float* yb = g_y + ((size_t)b * NE) * NL + t;
  float acc = 0.f;
  #pragma unroll 8
  for (int e = 0; e < NE; ++e) acc += yb[(size_t)e * NL] * __ldg(&sw[e]);
  g_s[b * NL + t] = acc;
}

// ---------------------------------------------------------------------------
// out: fused candidates + softmax over widths {1,2,3} + 2x avg-pool
// ---------------------------------------------------------------------------
__global__ __launch_bounds__(256) void out_kernel(float* __restrict__ out) {
  int idx = blockIdx.x * 256 + threadIdx.x;   // (b*NE+e)*4096 + to
  int to = idx & 4095;
  int be = idx >> 12;
  int b  = be >> 9;

  const float* y = g_y + (size_t)be * NL;
  const float* s = g_s + b * NL;

  int t0 = to * 2;
  float s0 = s[t0], s1 = s[t0 + 1];
  float y0 = y[t0], y1 = y[t0 + 1];
  float sc2 = 0.5f * (s0 + s1);
  float c2  = 0.5f * (y0 + y1);

  float r = 0.f;
  #pragma unroll
  for (int h = 0; h < 2; ++h) {
    int t = t0 + h;
    float sc1 = h ? s1 : s0;
    float c1  = h ? y1 : y0;
    float sc3, c3;
    if (t < 8190) {
      int bb = (t / 3) * 3;
      sc3 = (s[bb] + s[bb + 1] + s[bb + 2]) * (1.f / 3.f);
      c3  = (y[bb] + y[bb + 1] + y[bb + 2]) * (1.f / 3.f);
    } else { sc3 = 0.f; c3 = 0.f; }
    float m  = fmaxf(sc1, fmaxf(sc2, sc3));
    float e1 = __expf(sc1 - m);
    float e2 = __expf(sc2 - m);
    float e3 = __expf(sc3 - m);
    float inv = 1.f / (e1 + e2 + e3);
    r += (e1 * c1 + e2 * c2 + e3 * c3) * inv;
  }
  out[idx] = 0.5f * r;
}

// ---------------------------------------------------------------------------
extern "C" void kernel_launch(void* const* d_in, const int* in_sizes, int n_in,
                              void* d_out, int out_size) {
  const float* x  = (const float*)d_in[0];
  const float* cw = (const float*)d_in[1];
  const float* cb = (const float*)d_in[2];
  const float* sw = (const float*)d_in[3];
  float* out = (float*)d_out;

  cudaFuncSetAttribute(conv_mma, cudaFuncAttributeMaxDynamicSharedMemorySize, SMEM_SZ);

  prep_w<<<NE * NE * 5 / 256, 256>>>(cw);
  prep_x<<<dim3(XL / 32, NE / 32, NB), 256>>>(x);
  conv_mma<<<dim3(4 * (NL / 128), NB), 256, SMEM_SZ>>>(cb);
  score_kernel<<<dim3(NL / 256, NB), 256>>>(sw);
  out_kernel<<<NB * NE * (NL / 2) / 256, 256>>>(out);
}

// round 7
// speedup vs baseline: 4.0472x; 2.1579x over previous
#include <cuda_runtime.h>
#include <cuda_fp16.h>
#include <cstdint>

#define NB  8
#define NE  512
#define NL  8192
#define NLC 8188
#define XL  8448            // NL + 256 pad rows (zeroed)

// ---- conv GEMM tiling (mma.sync fp16 2-pass) ----
#define KCH   64                    // K elems per stage chunk
#define MAT_BYTES 16384             // 128 rows x 128B
#define STAGE_BYTES (3 * MAT_BYTES) // Wh | Xh | Xl
#define NSTAGE 4
#define SMEM_SZ (1024 + NSTAGE * STAGE_BYTES)
#define ITERS 40                    // 2560 / 64

// ---- scratch (__device__ globals; no runtime allocation) ----
__device__ __half g_xt_hi[(size_t)NB * XL * NE];
__device__ __half g_xt_lo[(size_t)NB * XL * NE];
__device__ __half g_wt_h[NE * NE * 5];
__device__ float g_y[(size_t)NB * NE * NL];
__device__ float g_s[NB * NL];

// ---------------------------------------------------------------------------
__device__ __forceinline__ uint32_t swz(uint32_t o) { return o ^ ((o >> 3) & 0x70); }

__device__ __forceinline__ void cp16(uint32_t dst, const void* src) {
  asm volatile("cp.async.cg.shared.global [%0], [%1], 16;" :: "r"(dst), "l"(src));
}

__device__ __forceinline__ void ldsm4(uint32_t& r0, uint32_t& r1, uint32_t& r2,
                                      uint32_t& r3, uint32_t addr) {
  asm volatile("ldmatrix.sync.aligned.m8n8.x4.shared.b16 {%0,%1,%2,%3}, [%4];"
               : "=r"(r0), "=r"(r1), "=r"(r2), "=r"(r3) : "r"(addr));
}

__device__ __forceinline__ void mma16816(float* d, const uint32_t* a,
                                         uint32_t b0, uint32_t b1) {
  asm volatile(
    "mma.sync.aligned.m16n8k16.row.col.f32.f16.f16.f32 "
    "{%0,%1,%2,%3}, {%4,%5,%6,%7}, {%8,%9}, {%0,%1,%2,%3};"
    : "+f"(d[0]), "+f"(d[1]), "+f"(d[2]), "+f"(d[3])
    : "r"(a[0]), "r"(a[1]), "r"(a[2]), "r"(a[3]), "r"(b0), "r"(b1));
}

// ---------------------------------------------------------------------------
__global__ __launch_bounds__(256) void zero_s() {
  g_s[blockIdx.x * 256 + threadIdx.x] = 0.f;
}

// prep_w: conv_w [E][E][5] fp32 -> wt_h[e][k*512+ci] fp16
__global__ __launch_bounds__(256) void prep_w(const float* __restrict__ w) {
  int idx = blockIdx.x * 256 + threadIdx.x;       // e*2560 + (k*512+ci)
  int e = idx / 2560, kk = idx - e * 2560;
  int k = kk >> 9, ci = kk & 511;
  g_wt_h[idx] = __float2half_rn(w[e * 2560 + ci * 5 + k]);
}

// prep_x: x [B][E][L] fp32 -> xt_{hi,lo}[b][t][ci] fp16 split (transpose),
// rows t in [NL, XL) zeroed.
__global__ __launch_bounds__(256) void prep_x(const float* __restrict__ x) {
  __shared__ float tile[32][33];
  int t0 = blockIdx.x * 32;
  int c0 = blockIdx.y * 32;
  int b  = blockIdx.z;
  int tx = threadIdx.x & 31, ty = threadIdx.x >> 5;
  #pragma unroll
  for (int j = 0; j < 4; ++j) {
    int t = t0 + tx, c = c0 + ty + 8 * j;
    tile[ty + 8 * j][tx] = (t < NL) ? x[((size_t)b * NE + c) * NL + t] : 0.f;
  }
  __syncthreads();
  #pragma unroll
  for (int j = 0; j < 4; ++j) {
    int t = t0 + ty + 8 * j;
    float v = tile[tx][ty + 8 * j];
    __half h = __float2half_rn(v);
    size_t off = ((size_t)b * XL + t) * NE + c0 + tx;
    g_xt_hi[off] = h;
    g_xt_lo[off] = __float2half_rn(v - __half2float(h));
  }
}

// ---------------------------------------------------------------------------
// conv_mma: y[e,t] = bias[e] + sum_{k,ci} W[e,ci,k]*x[ci,t+k]
// CTA 128x128, warps 2x4 (64x32 each), fp16 2-pass (Wh*Xh + Wh*Xl).
// 4-stage cp.async pipeline, SW128-swizzled smem. Score fused into epilogue.
// ---------------------------------------------------------------------------
__device__ __forceinline__ void load_stage(int i, uint32_t sb, int tid,
                                           int e0, int b, int t0) {
  int k  = i >> 3;
  int c0 = (i & 7) * KCH;
  const __half* wh = g_wt_h  + (size_t)e0 * 2560 + k * 512 + c0;
  const __half* xh = g_xt_hi + ((size_t)b * XL + t0 + k) * NE + c0;
  const __half* xl = g_xt_lo + ((size_t)b * XL + t0 + k) * NE + c0;
  #pragma unroll
  for (int j = 0; j < 4; ++j) {
    int q = tid + j * 256;          // 0..1023
    int r = q >> 3, ch = q & 7;     // row 0..127, 16B chunk 0..7
    uint32_t d = swz((uint32_t)(r * 128 + ch * 16));
    cp16(sb + 0 * MAT_BYTES + d, wh + (size_t)r * 2560 + ch * 8);
    cp16(sb + 1 * MAT_BYTES + d, xh + (size_t)r * NE + ch * 8);
    cp16(sb + 2 * MAT_BYTES + d, xl + (size_t)r * NE + ch * 8);
  }
  asm volatile("cp.async.commit_group;" ::: "memory");
}

__global__ __launch_bounds__(256, 1) void conv_mma(const float* __restrict__ bias,
                                                   const float* __restrict__ sw) {
  extern __shared__ char dsm[];
  uint32_t raw  = (uint32_t)__cvta_generic_to_shared(dsm);
  uint32_t base = (raw + 1023) & ~1023u;

  const int tid = threadIdx.x;
  const int mt = blockIdx.x & 3;
  const int tt = blockIdx.x >> 2;
  const int b  = blockIdx.y;
  const int e0 = mt * 128;
  const int t0 = tt * 128;

  const int l   = tid & 31;
  const int wrp = tid >> 5;
  const int m0w = (wrp >> 2) * 64;
  const int n0w = (wrp & 3) * 32;

  const int rA = (l & 15);
  const int cA = (l >> 4) * 16;
  const int rB = (l & 7) + ((l >> 4) & 1) * 8;
  const int cB = ((l >> 3) & 1) * 16;

  float acc[4][4][4];
  #pragma unroll
  for (int i = 0; i < 4; ++i)
    #pragma unroll
    for (int j = 0; j < 4; ++j)
      #pragma unroll
      for (int q = 0; q < 4; ++q) acc[i][j][q] = 0.f;

  load_stage(0, base + 1024, tid, e0, b, t0);
  load_stage(1, base + 1024 + STAGE_BYTES, tid, e0, b, t0);
  load_stage(2, base + 1024 + 2 * STAGE_BYTES, tid, e0, b, t0);

  for (int i = 0; i < ITERS; ++i) {
    if (i >= ITERS - 2) asm volatile("cp.async.wait_group 0;" ::: "memory");
    else                asm volatile("cp.async.wait_group 2;" ::: "memory");
    __syncthreads();
    if (i + 3 < ITERS)
      load_stage(i + 3, base + 1024 + (uint32_t)((i + 3) % NSTAGE) * STAGE_BYTES,
                 tid, e0, b, t0);

    uint32_t sb = base + 1024 + (uint32_t)(i % NSTAGE) * STAGE_BYTES;
    uint32_t sW = sb, sXh = sb + MAT_BYTES, sXl = sb + 2 * MAT_BYTES;

    #pragma unroll
    for (int ks = 0; ks < 4; ++ks) {
      const int kb = ks * 32;   // byte offset of this k16 within 128B row
      uint32_t a[4][4], bh[4][2], bl[4][2];
      #pragma unroll
      for (int mi = 0; mi < 4; ++mi) {
        uint32_t off = swz((uint32_t)((m0w + mi * 16 + rA) * 128 + kb + cA));
        ldsm4(a[mi][0], a[mi][1], a[mi][2], a[mi][3], sW + off);
      }
      #pragma unroll
      for (int nj = 0; nj < 2; ++nj) {
        uint32_t off = swz((uint32_t)((n0w + nj * 16 + rB) * 128 + kb + cB));
        ldsm4(bh[nj * 2][0], bh[nj * 2][1], bh[nj * 2 + 1][0], bh[nj * 2 + 1][1],
              sXh + off);
      }
      #pragma unroll
      for (int mi = 0; mi < 4; ++mi)
        #pragma unroll
        for (int ni = 0; ni < 4; ++ni)
          mma16816(acc[mi][ni], a[mi], bh[ni][0], bh[ni][1]);

      #pragma unroll
      for (int nj = 0; nj < 2; ++nj) {
        uint32_t off = swz((uint32_t)((n0w + nj * 16 + rB) * 128 + kb + cB));
        ldsm4(bl[nj * 2][0], bl[nj * 2][1], bl[nj * 2 + 1][0], bl[nj * 2 + 1][1],
              sXl + off);
      }
      #pragma unroll
      for (int mi = 0; mi < 4; ++mi)
        #pragma unroll
        for (int ni = 0; ni < 4; ++ni)
          mma16816(acc[mi][ni], a[mi], bl[ni][0], bl[ni][1]);
    }
  }

  // ---- epilogue: store y (+bias, zero tail) and fused score reduction ----
  // lane l of warp: rows e = e0+m0w+mi*16+(l>>2)+8*half, cols t = t0+n0w+ni*8+2(l&3)+p
  float sacc[8];
  #pragma unroll
  for (int j = 0; j < 8; ++j) sacc[j] = 0.f;

  #pragma unroll
  for (int mi = 0; mi < 4; ++mi) {
    #pragma unroll
    for (int half = 0; half < 2; ++half) {
      int e = e0 + m0w + mi * 16 + (l >> 2) + half * 8;
      float bv = bias[e];
      float swv = __ldg(&sw[e]);
      float* yrow = g_y + ((size_t)(b * NE + e)) * NL;
      #pragma unroll
      for (int ni = 0; ni < 4; ++ni) {
        int t = t0 + n0w + ni * 8 + 2 * (l & 3);
        float2 v;
        if (t < NLC) {
          v.x = acc[mi][ni][half * 2 + 0] + bv;
          v.y = acc[mi][ni][half * 2 + 1] + bv;
        } else { v.x = 0.f; v.y = 0.f; }
        *reinterpret_cast<float2*>(yrow + t) = v;
        sacc[ni * 2 + 0] += swv * v.x;
        sacc[ni * 2 + 1] += swv * v.y;
      }
    }
  }
  // reduce over the 8 lane-groups sharing (l&3): strides 4, 8, 16
  #pragma unroll
  for (int st = 4; st <= 16; st <<= 1)
    #pragma unroll
    for (int j = 0; j < 8; ++j)
      sacc[j] += __shfl_xor_sync(0xFFFFFFFFu, sacc[j], st);

  if (l < 4) {
    float* srow = g_s + b * NL;
    #pragma unroll
    for (int j = 0; j < 8; ++j) {
      int t = t0 + n0w + (j >> 1) * 8 + 2 * l + (j & 1);
      atomicAdd(srow + t, sacc[j]);
    }
  }
}

// ---------------------------------------------------------------------------
// out: fused candidates + softmax over widths {1,2,3} + 2x avg-pool
// ---------------------------------------------------------------------------
__global__ __launch_bounds__(256) void out_kernel(float* __restrict__ out) {
  int idx = blockIdx.x * 256 + threadIdx.x;   // (b*NE+e)*4096 + to
  int to = idx & 4095;
  int be = idx >> 12;
  int b  = be >> 9;

  const float* y = g_y + (size_t)be * NL;
  const float* s = g_s + b * NL;

  int t0 = to * 2;
  float s0 = s[t0], s1 = s[t0 + 1];
  float y0 = y[t0], y1 = y[t0 + 1];
  float sc2 = 0.5f * (s0 + s1);
  float c2  = 0.5f * (y0 + y1);

  float r = 0.f;
  #pragma unroll
  for (int h = 0; h < 2; ++h) {
    int t = t0 + h;
    float sc1 = h ? s1 : s0;
    float c1  = h ? y1 : y0;
    float sc3, c3;
    if (t < 8190) {
      int bb = (t / 3) * 3;
      sc3 = (s[bb] + s[bb + 1] + s[bb + 2]) * (1.f / 3.f);
      c3  = (y[bb] + y[bb + 1] + y[bb + 2]) * (1.f / 3.f);
    } else { sc3 = 0.f; c3 = 0.f; }
    float m  = fmaxf(sc1, fmaxf(sc2, sc3));
    float e1 = __expf(sc1 - m);
    float e2 = __expf(sc2 - m);
    float e3 = __expf(sc3 - m);
    float inv = 1.f / (e1 + e2 + e3);
    r += (e1 * c1 + e2 * c2 + e3 * c3) * inv;
  }
  out[idx] = 0.5f * r;
}

// ---------------------------------------------------------------------------
extern "C" void kernel_launch(void* const* d_in, const int* in_sizes, int n_in,
                              void* d_out, int out_size) {
  const float* x  = (const float*)d_in[0];
  const float* cw = (const float*)d_in[1];
  const float* cb = (const float*)d_in[2];
  const float* sw = (const float*)d_in[3];
  float* out = (float*)d_out;

  cudaFuncSetAttribute(conv_mma, cudaFuncAttributeMaxDynamicSharedMemorySize, SMEM_SZ);

  zero_s<<<NB * NL / 256, 256>>>();
  prep_w<<<NE * NE * 5 / 256, 256>>>(cw);
  prep_x<<<dim3(XL / 32, NE / 32, NB), 256>>>(x);
  conv_mma<<<dim3(4 * (NL / 128), NB), 256, SMEM_SZ>>>(cb, sw);
  out_kernel<<<NB * NE * (NL / 2) / 256, 256>>>(out);
}

// round 8
// speedup vs baseline: 6.0413x; 1.4927x over previous
#include <cuda_runtime.h>
#include <cuda_fp16.h>
#include <cstdint>

#define NB  8
#define NE  512
#define NL  8192
#define NLC 8188
#define XL  8448            // NL + 256 pad rows (zeroed)

// ---- conv GEMM tiling (mma.sync fp16 single-pass) ----
#define KCH   64                    // K elems per stage chunk
#define MAT_BYTES 16384             // 128 rows x 128B
#define STAGE_BYTES (2 * MAT_BYTES) // Wh | Xh
#define NSTAGE 6
#define SMEM_SZ (1024 + NSTAGE * STAGE_BYTES)   // 197,632 B
#define ITERS 40                    // 2560 / 64

// ---- scratch (__device__ globals; no runtime allocation) ----
__device__ __half g_xt_hi[(size_t)NB * XL * NE];
__device__ __half g_wt_h[NE * NE * 5];
__device__ float g_y[(size_t)NB * NE * NL];
__device__ float g_s[NB * NL];

// ---------------------------------------------------------------------------
__device__ __forceinline__ uint32_t swz(uint32_t o) { return o ^ ((o >> 3) & 0x70); }

__device__ __forceinline__ void cp16(uint32_t dst, const void* src) {
  asm volatile("cp.async.cg.shared.global [%0], [%1], 16;" :: "r"(dst), "l"(src));
}

__device__ __forceinline__ void ldsm4(uint32_t& r0, uint32_t& r1, uint32_t& r2,
                                      uint32_t& r3, uint32_t addr) {
  asm volatile("ldmatrix.sync.aligned.m8n8.x4.shared.b16 {%0,%1,%2,%3}, [%4];"
               : "=r"(r0), "=r"(r1), "=r"(r2), "=r"(r3) : "r"(addr));
}

__device__ __forceinline__ void mma16816(float* d, const uint32_t* a,
                                         uint32_t b0, uint32_t b1) {
  asm volatile(
    "mma.sync.aligned.m16n8k16.row.col.f32.f16.f16.f32 "
    "{%0,%1,%2,%3}, {%4,%5,%6,%7}, {%8,%9}, {%0,%1,%2,%3};"
    : "+f"(d[0]), "+f"(d[1]), "+f"(d[2]), "+f"(d[3])
    : "r"(a[0]), "r"(a[1]), "r"(a[2]), "r"(a[3]), "r"(b0), "r"(b1));
}

// ---------------------------------------------------------------------------
__global__ __launch_bounds__(256) void zero_s() {
  g_s[blockIdx.x * 256 + threadIdx.x] = 0.f;
}

// prep_w: conv_w [E][E][5] fp32 -> wt_h[e][k*512+ci] fp16
__global__ __launch_bounds__(256) void prep_w(const float* __restrict__ w) {
  int idx = blockIdx.x * 256 + threadIdx.x;       // e*2560 + (k*512+ci)
  int e = idx / 2560, kk = idx - e * 2560;
  int k = kk >> 9, ci = kk & 511;
  g_wt_h[idx] = __float2half_rn(w[e * 2560 + ci * 5 + k]);
}

// prep_x: x [B][E][L] fp32 -> xt_hi[b][t][ci] fp16 (transpose),
// rows t in [NL, XL) zeroed.
__global__ __launch_bounds__(256) void prep_x(const float* __restrict__ x) {
  __shared__ float tile[32][33];
  int t0 = blockIdx.x * 32;
  int c0 = blockIdx.y * 32;
  int b  = blockIdx.z;
  int tx = threadIdx.x & 31, ty = threadIdx.x >> 5;
  #pragma unroll
  for (int j = 0; j < 4; ++j) {
    int t = t0 + tx, c = c0 + ty + 8 * j;
    tile[ty + 8 * j][tx] = (t < NL) ? x[((size_t)b * NE + c) * NL + t] : 0.f;
  }
  __syncthreads();
  #pragma unroll
  for (int j = 0; j < 4; ++j) {
    int t = t0 + ty + 8 * j;
    float v = tile[tx][ty + 8 * j];
    size_t off = ((size_t)b * XL + t) * NE + c0 + tx;
    g_xt_hi[off] = __float2half_rn(v);
  }
}

// ---------------------------------------------------------------------------
// conv_mma: y[e,t] = bias[e] + sum_{k,ci} W[e,ci,k]*x[ci,t+k]
// CTA 128x128, warps 2x4 (64x32 each), fp16 single-pass Wh*Xh.
// 6-stage cp.async pipeline, SW128-swizzled smem. Score fused into epilogue.
// ---------------------------------------------------------------------------
__device__ __forceinline__ void load_stage(int i, uint32_t sb, int tid,
                                           int e0, int b, int t0) {
  int k  = i >> 3;
  int c0 = (i & 7) * KCH;
  const __half* wh = g_wt_h  + (size_t)e0 * 2560 + k * 512 + c0;
  const __half* xh = g_xt_hi + ((size_t)b * XL + t0 + k) * NE + c0;
  #pragma unroll
  for (int j = 0; j < 4; ++j) {
    int q = tid + j * 256;          // 0..1023
    int r = q >> 3, ch = q & 7;     // row 0..127, 16B chunk 0..7
    uint32_t d = swz((uint32_t)(r * 128 + ch * 16));
    cp16(sb + 0 * MAT_BYTES + d, wh + (size_t)r * 2560 + ch * 8);
    cp16(sb + 1 * MAT_BYTES + d, xh + (size_t)r * NE + ch * 8);
  }
  asm volatile("cp.async.commit_group;" ::: "memory");
}

__global__ __launch_bounds__(256, 1) void conv_mma(const float* __restrict__ bias,
                                                   const float* __restrict__ sw) {
  extern __shared__ char dsm[];
  uint32_t raw  = (uint32_t)__cvta_generic_to_shared(dsm);
  uint32_t base = (raw + 1023) & ~1023u;

  const int tid = threadIdx.x;
  const int mt = blockIdx.x & 3;
  const int tt = blockIdx.x >> 2;
  const int b  = blockIdx.y;
  const int e0 = mt * 128;
  const int t0 = tt * 128;

  const int l   = tid & 31;
  const int wrp = tid >> 5;
  const int m0w = (wrp >> 2) * 64;
  const int n0w = (wrp & 3) * 32;

  const int rA = (l & 15);
  const int cA = (l >> 4) * 16;
  const int rB = (l & 7) + ((l >> 4) & 1) * 8;
  const int cB = ((l >> 3) & 1) * 16;

  float acc[4][4][4];
  #pragma unroll
  for (int i = 0; i < 4; ++i)
    #pragma unroll
    for (int j = 0; j < 4; ++j)
      #pragma unroll
      for (int q = 0; q < 4; ++q) acc[i][j][q] = 0.f;

  #pragma unroll
  for (int p = 0; p < NSTAGE - 1; ++p)
    load_stage(p, base + 1024 + (uint32_t)p * STAGE_BYTES, tid, e0, b, t0);

  for (int i = 0; i < ITERS; ++i) {
    // issued through min(i + NSTAGE-2, ITERS-1); need stage i complete
    if (i >= ITERS - (NSTAGE - 2)) asm volatile("cp.async.wait_group 0;" ::: "memory");
    else                           asm volatile("cp.async.wait_group %0;" :: "n"(NSTAGE - 2) : "memory");
    __syncthreads();
    if (i + NSTAGE - 1 < ITERS)
      load_stage(i + NSTAGE - 1,
                 base + 1024 + (uint32_t)((i + NSTAGE - 1) % NSTAGE) * STAGE_BYTES,
                 tid, e0, b, t0);

    uint32_t sb = base + 1024 + (uint32_t)(i % NSTAGE) * STAGE_BYTES;
    uint32_t sW = sb, sXh = sb + MAT_BYTES;

    #pragma unroll
    for (int ks = 0; ks < 4; ++ks) {
      const int kb = ks * 32;   // byte offset of this k16 within 128B row
      uint32_t a[4][4], bh[4][2];
      #pragma unroll
      for (int mi = 0; mi < 4; ++mi) {
        uint32_t off = swz((uint32_t)((m0w + mi * 16 + rA) * 128 + kb + cA));
        ldsm4(a[mi][0], a[mi][1], a[mi][2], a[mi][3], sW + off);
      }
      #pragma unroll
      for (int nj = 0; nj < 2; ++nj) {
        uint32_t off = swz((uint32_t)((n0w + nj * 16 + rB) * 128 + kb + cB));
        ldsm4(bh[nj * 2][0], bh[nj * 2][1], bh[nj * 2 + 1][0], bh[nj * 2 + 1][1],
              sXh + off);
      }
      #pragma unroll
      for (int mi = 0; mi < 4; ++mi)
        #pragma unroll
        for (int ni = 0; ni < 4; ++ni)
          mma16816(acc[mi][ni], a[mi], bh[ni][0], bh[ni][1]);
    }
  }

  // ---- epilogue: store y (+bias, zero tail) and fused score reduction ----
  float sacc[8];
  #pragma unroll
  for (int j = 0; j < 8; ++j) sacc[j] = 0.f;

  #pragma unroll
  for (int mi = 0; mi < 4; ++mi) {
    #pragma unroll
    for (int half = 0; half < 2; ++half) {
      int e = e0 + m0w + mi * 16 + (l >> 2) + half * 8;
      float bv = bias[e];
      float swv = __ldg(&sw[e]);
      float* yrow = g_y + ((size_t)(b * NE + e)) * NL;
      #pragma unroll
      for (int ni = 0; ni < 4; ++ni) {
        int t = t0 + n0w + ni * 8 + 2 * (l & 3);
        float2 v;
        if (t < NLC) {
          v.x = acc[mi][ni][half * 2 + 0] + bv;
          v.y = acc[mi][ni][half * 2 + 1] + bv;
        } else { v.x = 0.f; v.y = 0.f; }
        *reinterpret_cast<float2*>(yrow + t) = v;
        sacc[ni * 2 + 0] += swv * v.x;
        sacc[ni * 2 + 1] += swv * v.y;
      }
    }
  }
  // reduce over the 8 lane-groups sharing (l&3): strides 4, 8, 16
  #pragma unroll
  for (int st = 4; st <= 16; st <<= 1)
    #pragma unroll
    for (int j = 0; j < 8; ++j)
      sacc[j] += __shfl_xor_sync(0xFFFFFFFFu, sacc[j], st);

  if (l < 4) {
    float* srow = g_s + b * NL;
    #pragma unroll
    for (int j = 0; j < 8; ++j) {
      int t = t0 + n0w + (j >> 1) * 8 + 2 * l + (j & 1);
      atomicAdd(srow + t, sacc[j]);
    }
  }
}

// ---------------------------------------------------------------------------
// out: fused candidates + softmax over widths {1,2,3} + 2x avg-pool
// ---------------------------------------------------------------------------
__global__ __launch_bounds__(256) void out_kernel(float* __restrict__ out) {
  int idx = blockIdx.x * 256 + threadIdx.x;   // (b*NE+e)*4096 + to
  int to = idx & 4095;
  int be = idx >> 12;
  int b  = be >> 9;

  const float* y = g_y + (size_t)be * NL;
  const float* s = g_s + b * NL;

  int t0 = to * 2;
  float s0 = s[t0], s1 = s[t0 + 1];
  float y0 = y[t0], y1 = y[t0 + 1];
  float sc2 = 0.5f * (s0 + s1);
  float c2  = 0.5f * (y0 + y1);

  float r = 0.f;
  #pragma unroll
  for (int h = 0; h < 2; ++h) {
    int t = t0 + h;
    float sc1 = h ? s1 : s0;
    float c1  = h ? y1 : y0;
    float sc3, c3;
    if (t < 8190) {
      int bb = (t / 3) * 3;
      sc3 = (s[bb] + s[bb + 1] + s[bb + 2]) * (1.f / 3.f);
      c3  = (y[bb] + y[bb + 1] + y[bb + 2]) * (1.f / 3.f);
    } else { sc3 = 0.f; c3 = 0.f; }
    float m  = fmaxf(sc1, fmaxf(sc2, sc3));
    float e1 = __expf(sc1 - m);
    float e2 = __expf(sc2 - m);
    float e3 = __expf(sc3 - m);
    float inv = 1.f / (e1 + e2 + e3);
    r += (e1 * c1 + e2 * c2 + e3 * c3) * inv;
  }
  out[idx] = 0.5f * r;
}

// ---------------------------------------------------------------------------
extern "C" void kernel_launch(void* const* d_in, const int* in_sizes, int n_in,
                              void* d_out, int out_size) {
  const float* x  = (const float*)d_in[0];
  const float* cw = (const float*)d_in[1];
  const float* cb = (const float*)d_in[2];
  const float* sw = (const float*)d_in[3];
  float* out = (float*)d_out;

  cudaFuncSetAttribute(conv_mma, cudaFuncAttributeMaxDynamicSharedMemorySize, SMEM_SZ);

  zero_s<<<NB * NL / 256, 256>>>();
  prep_w<<<NE * NE * 5 / 256, 256>>>(cw);
  prep_x<<<dim3(XL / 32, NE / 32, NB), 256>>>(x);
  conv_mma<<<dim3(4 * (NL / 128), NB), 256, SMEM_SZ>>>(cb, sw);
  out_kernel<<<NB * NE * (NL / 2) / 256, 256>>>(out);
}

// round 10
// speedup vs baseline: 6.9605x; 1.1521x over previous
#include <cuda_runtime.h>
#include <cuda_fp16.h>
#include <cstdint>

#define NB  8
#define NE  512
#define NL  8192
#define NLC 8188
#define XL  8448            // NL + 256 pad rows (zeroed)

// ---- conv GEMM tiling: CTA 128 x 256, warp 64 x 64, fp16 single-pass ----
#define KCH   64
#define W_BYTES 16384               // 128 rows x 128B
#define X_BYTES 32768               // 256 rows x 128B
#define STAGE_BYTES (W_BYTES + X_BYTES)
#define NSTAGE 4
#define SMEM_SZ (1024 + NSTAGE * STAGE_BYTES)   // 197,632 B
#define ITERS 40                    // 2560 / 64

// ---- scratch (__device__ globals; no runtime allocation) ----
__device__ __half g_xt_hi[(size_t)NB * XL * NE];
__device__ __half g_wt_h[NE * NE * 5];
__device__ float g_y[(size_t)NB * NE * NL];
__device__ float g_s[NB * NL];

// ---------------------------------------------------------------------------
__device__ __forceinline__ uint32_t swz(uint32_t o) { return o ^ ((o >> 3) & 0x70); }

__device__ __forceinline__ void cp16(uint32_t dst, const void* src) {
  asm volatile("cp.async.cg.shared.global [%0], [%1], 16;" :: "r"(dst), "l"(src));
}

__device__ __forceinline__ void ldsm4(uint32_t& r0, uint32_t& r1, uint32_t& r2,
                                      uint32_t& r3, uint32_t addr) {
  asm volatile("ldmatrix.sync.aligned.m8n8.x4.shared.b16 {%0,%1,%2,%3}, [%4];"
               : "=r"(r0), "=r"(r1), "=r"(r2), "=r"(r3) : "r"(addr));
}

__device__ __forceinline__ void mma16816(float* d, const uint32_t* a,
                                         uint32_t b0, uint32_t b1) {
  asm volatile(
    "mma.sync.aligned.m16n8k16.row.col.f32.f16.f16.f32 "
    "{%0,%1,%2,%3}, {%4,%5,%6,%7}, {%8,%9}, {%0,%1,%2,%3};"
    : "+f"(d[0]), "+f"(d[1]), "+f"(d[2]), "+f"(d[3])
    : "r"(a[0]), "r"(a[1]), "r"(a[2]), "r"(a[3]), "r"(b0), "r"(b1));
}

// ---------------------------------------------------------------------------
__global__ __launch_bounds__(256) void zero_s() {
  g_s[blockIdx.x * 256 + threadIdx.x] = 0.f;
}

// prep_w: conv_w [E][E][5] fp32 -> wt_h[e][k*512+ci] fp16
__global__ __launch_bounds__(256) void prep_w(const float* __restrict__ w) {
  int idx = blockIdx.x * 256 + threadIdx.x;       // e*2560 + (k*512+ci)
  int e = idx / 2560, kk = idx - e * 2560;
  int k = kk >> 9, ci = kk & 511;
  g_wt_h[idx] = __float2half_rn(w[e * 2560 + ci * 5 + k]);
}

// prep_x: x [B][E][L] fp32 -> xt_hi[b][t][ci] fp16 (transpose),
// rows t in [NL, XL) zeroed.
__global__ __launch_bounds__(256) void prep_x(const float* __restrict__ x) {
  __shared__ float tile[32][33];
  int t0 = blockIdx.x * 32;
  int c0 = blockIdx.y * 32;
  int b  = blockIdx.z;
  int tx = threadIdx.x & 31, ty = threadIdx.x >> 5;
  #pragma unroll
  for (int j = 0; j < 4; ++j) {
    int t = t0 + tx, c = c0 + ty + 8 * j;
    tile[ty + 8 * j][tx] = (t < NL) ? x[((size_t)b * NE + c) * NL + t] : 0.f;
  }
  __syncthreads();
  #pragma unroll
  for (int j = 0; j < 4; ++j) {
    int t = t0 + ty + 8 * j;
    float v = tile[tx][ty + 8 * j];
    size_t off = ((size_t)b * XL + t) * NE + c0 + tx;
    g_xt_hi[off] = __float2half_rn(v);
  }
}

// ---------------------------------------------------------------------------
// conv_mma: y[e,t] = bias[e] + sum_{k,ci} W[e,ci,k]*x[ci,t+k]
// CTA 128x256, 8 warps 2x4 (64x64 each), fp16 single-pass.
// 4-stage cp.async pipeline, SW128-swizzled smem. Score fused into epilogue.
// ---------------------------------------------------------------------------
__device__ __forceinline__ void load_stage(int i, uint32_t sb, int tid,
                                           int e0, int b, int t0) {
  int k  = i >> 3;
  int c0 = (i & 7) * KCH;
  const __half* wh = g_wt_h  + (size_t)e0 * 2560 + k * 512 + c0;
  const __half* xh = g_xt_hi + ((size_t)b * XL + t0 + k) * NE + c0;
  #pragma unroll
  for (int j = 0; j < 4; ++j) {                 // W: 128 rows x 8 chunks
    int q = tid + j * 256;
    int r = q >> 3, ch = q & 7;
    uint32_t d = swz((uint32_t)(r * 128 + ch * 16));
    cp16(sb + d, wh + (size_t)r * 2560 + ch * 8);
  }
  #pragma unroll
  for (int j = 0; j < 8; ++j) {                 // X: 256 rows x 8 chunks
    int q = tid + j * 256;
    int r = q >> 3, ch = q & 7;
    uint32_t d = swz((uint32_t)(r * 128 + ch * 16));
    cp16(sb + W_BYTES + d, xh + (size_t)r * NE + ch * 8);
  }
  asm volatile("cp.async.commit_group;" ::: "memory");
}

__global__ __launch_bounds__(256, 1) void conv_mma(const float* __restrict__ bias,
                                                   const float* __restrict__ sw) {
  extern __shared__ char dsm[];
  uint32_t raw  = (uint32_t)__cvta_generic_to_shared(dsm);
  uint32_t base = (raw + 1023) & ~1023u;

  const int tid = threadIdx.x;
  const int mt = blockIdx.x & 3;
  const int tt = blockIdx.x >> 2;
  const int b  = blockIdx.y;
  const int e0 = mt * 128;
  const int t0 = tt * 256;

  const int l   = tid & 31;
  const int wrp = tid >> 5;
  const int m0w = (wrp >> 2) * 64;
  const int n0w = (wrp & 3) * 64;

  const int rA = (l & 15);
  const int cA = (l >> 4) * 16;
  const int rB = (l & 7) + ((l >> 4) & 1) * 8;
  const int cB = ((l >> 3) & 1) * 16;

  float acc[4][8][4];
  #pragma unroll
  for (int i = 0; i < 4; ++i)
    #pragma unroll
    for (int j = 0; j < 8; ++j)
      #pragma unroll
      for (int q = 0; q < 4; ++q) acc[i][j][q] = 0.f;

  #pragma unroll
  for (int p = 0; p < NSTAGE - 1; ++p)
    load_stage(p, base + 1024 + (uint32_t)p * STAGE_BYTES, tid, e0, b, t0);

  for (int i = 0; i < ITERS; ++i) {
    if (i >= ITERS - (NSTAGE - 2)) asm volatile("cp.async.wait_group 0;" ::: "memory");
    else                           asm volatile("cp.async.wait_group %0;" :: "n"(NSTAGE - 2) : "memory");
    __syncthreads();
    if (i + NSTAGE - 1 < ITERS)
      load_stage(i + NSTAGE - 1,
                 base + 1024 + (uint32_t)((i + NSTAGE - 1) % NSTAGE) * STAGE_BYTES,
                 tid, e0, b, t0);

    uint32_t sb = base + 1024 + (uint32_t)(i % NSTAGE) * STAGE_BYTES;
    uint32_t sW = sb, sX = sb + W_BYTES;

    #pragma unroll
    for (int ks = 0; ks < 4; ++ks) {
      const int kb = ks * 32;
      uint32_t a[4][4], bh[8][2];
      #pragma unroll
      for (int mi = 0; mi < 4; ++mi) {
        uint32_t off = swz((uint32_t)((m0w + mi * 16 + rA) * 128 + kb + cA));
        ldsm4(a[mi][0], a[mi][1], a[mi][2], a[mi][3], sW + off);
      }
      #pragma unroll
      for (int nj = 0; nj < 4; ++nj) {
        uint32_t off = swz((uint32_t)((n0w + nj * 16 + rB) * 128 + kb + cB));
        ldsm4(bh[nj * 2][0], bh[nj * 2][1], bh[nj * 2 + 1][0], bh[nj * 2 + 1][1],
              sX + off);
      }
      #pragma unroll
      for (int mi = 0; mi < 4; ++mi)
        #pragma unroll
        for (int ni = 0; ni < 8; ++ni)
          mma16816(acc[mi][ni], a[mi], bh[ni][0], bh[ni][1]);
    }
  }

  // ---- epilogue: store y (+bias, zero tail) and fused score reduction ----
  float sacc[16];
  #pragma unroll
  for (int j = 0; j < 16; ++j) sacc[j] = 0.f;

  #pragma unroll
  for (int mi = 0; mi < 4; ++mi) {
    #pragma unroll
    for (int half = 0; half < 2; ++half) {
      int e = e0 + m0w + mi * 16 + (l >> 2) + half * 8;
      float bv = bias[e];
      float swv = __ldg(&sw[e]);
      float* yrow = g_y + ((size_t)(b * NE + e)) * NL;
      #pragma unroll
      for (int ni = 0; ni < 8; ++ni) {
        int t = t0 + n0w + ni * 8 + 2 * (l & 3);
        float2 v;
        if (t < NLC) {
          v.x = acc[mi][ni][half * 2 + 0] + bv;
          v.y = acc[mi][ni][half * 2 + 1] + bv;
        } else { v.x = 0.f; v.y = 0.f; }
        *reinterpret_cast<float2*>(yrow + t) = v;
        sacc[ni * 2 + 0] += swv * v.x;
        sacc[ni * 2 + 1] += swv * v.y;
      }
    }
  }
  // reduce over the 8 lane-groups sharing (l&3): strides 4, 8, 16
  #pragma unroll
  for (int st = 4; st <= 16; st <<= 1)
    #pragma unroll
    for (int j = 0; j < 16; ++j)
      sacc[j] += __shfl_xor_sync(0xFFFFFFFFu, sacc[j], st);

  if (l < 4) {
    float* srow = g_s + b * NL;
    #pragma unroll
    for (int j = 0; j < 16; ++j) {
      int t = t0 + n0w + (j >> 1) * 8 + 2 * l + (j & 1);
      atomicAdd(srow + t, sacc[j]);
    }
  }
}

// ---------------------------------------------------------------------------
// out: fused candidates + softmax over widths {1,2,3} + 2x avg-pool
// ---------------------------------------------------------------------------
__global__ __launch_bounds__(256) void out_kernel(float* __restrict__ out) {
  int idx = blockIdx.x * 256 + threadIdx.x;   // (b*NE+e)*4096 + to
  int to = idx & 4095;
  int be = idx >> 12;
  int b  = be >> 9;

  const float* y = g_y + (size_t)be * NL;
  const float* s = g_s + b * NL;

  int t0 = to * 2;
  float s0 = s[t0], s1 = s[t0 + 1];
  float y0 = y[t0], y1 = y[t0 + 1];
  float sc2 = 0.5f * (s0 + s1);
  float c2  = 0.5f * (y0 + y1);

  float r = 0.f;
  #pragma unroll
  for (int h = 0; h < 2; ++h) {
    int t = t0 + h;
    float sc1 = h ? s1 : s0;
    float c1  = h ? y1 : y0;
    float sc3, c3;
    if (t < 8190) {
      int bb = (t / 3) * 3;
      sc3 = (s[bb] + s[bb + 1] + s[bb + 2]) * (1.f / 3.f);
      c3  = (y[bb] + y[bb + 1] + y[bb + 2]) * (1.f / 3.f);
    } else { sc3 = 0.f; c3 = 0.f; }
    float m  = fmaxf(sc1, fmaxf(sc2, sc3));
    float e1 = __expf(sc1 - m);
    float e2 = __expf(sc2 - m);
    float e3 = __expf(sc3 - m);
    float inv = 1.f / (e1 + e2 + e3);
    r += (e1 * c1 + e2 * c2 + e3 * c3) * inv;
  }
  out[idx] = 0.5f * r;
}

// ---------------------------------------------------------------------------
extern "C" void kernel_launch(void* const* d_in, const int* in_sizes, int n_in,
                              void* d_out, int out_size) {
  const float* x  = (const float*)d_in[0];
  const float* cw = (const float*)d_in[1];
  const float* cb = (const float*)d_in[2];
  const float* sw = (const float*)d_in[3];
  float* out = (float*)d_out;

  cudaFuncSetAttribute(conv_mma, cudaFuncAttributeMaxDynamicSharedMemorySize, SMEM_SZ);

  zero_s<<<NB * NL / 256, 256>>>();
  prep_w<<<NE * NE * 5 / 256, 256>>>(cw);
  prep_x<<<dim3(XL / 32, NE / 32, NB), 256>>>(x);
  conv_mma<<<dim3(4 * (NL / 256), NB), 256, SMEM_SZ>>>(cb, sw);
  out_kernel<<<NB * NE * (NL / 2) / 256, 256>>>(out);
}

// round 12
// speedup vs baseline: 7.2652x; 1.0438x over previous
#include <cuda_runtime.h>
#include <cuda_fp16.h>
#include <cstdint>

#define NB  8
#define NE  512
#define NL  8192
#define NLC 8188
#define XL  8448            // NL + 256 pad rows (zeroed)

// ---- conv GEMM tiling: CTA 128 x 256, warp 64 x 64, fp16 single-pass ----
// One pipeline stage carries K=128 as two back-to-back 64-chunks (halves).
#define W_BYTES 16384               // 128 rows x 128B (per half)
#define X_BYTES 32768               // 256 rows x 128B (per half)
#define HALF_BYTES (W_BYTES + X_BYTES)      // 48 KB
#define STAGE_BYTES (2 * HALF_BYTES)        // 96 KB
#define NSTAGE 2
#define SMEM_SZ (1024 + NSTAGE * STAGE_BYTES)   // 197,632 B
#define PITERS 20                   // 2560 / 128

// ---- scratch (__device__ globals; no runtime allocation) ----
__device__ __half g_xt_hi[(size_t)NB * XL * NE];
__device__ __half g_wt_h[NE * NE * 5];
__device__ float g_y[(size_t)NB * NE * NL];
__device__ float g_s[NB * NL];

// ---------------------------------------------------------------------------
__device__ __forceinline__ uint32_t swz(uint32_t o) { return o ^ ((o >> 3) & 0x70); }

__device__ __forceinline__ void cp16(uint32_t dst, const void* src) {
  asm volatile("cp.async.cg.shared.global [%0], [%1], 16;" :: "r"(dst), "l"(src));
}

__device__ __forceinline__ void ldsm4(uint32_t& r0, uint32_t& r1, uint32_t& r2,
                                      uint32_t& r3, uint32_t addr) {
  asm volatile("ldmatrix.sync.aligned.m8n8.x4.shared.b16 {%0,%1,%2,%3}, [%4];"
               : "=r"(r0), "=r"(r1), "=r"(r2), "=r"(r3) : "r"(addr));
}

__device__ __forceinline__ void mma16816(float* d, const uint32_t* a,
                                         uint32_t b0, uint32_t b1) {
  asm volatile(
    "mma.sync.aligned.m16n8k16.row.col.f32.f16.f16.f32 "
    "{%0,%1,%2,%3}, {%4,%5,%6,%7}, {%8,%9}, {%0,%1,%2,%3};"
    : "+f"(d[0]), "+f"(d[1]), "+f"(d[2]), "+f"(d[3])
    : "r"(a[0]), "r"(a[1]), "r"(a[2]), "r"(a[3]), "r"(b0), "r"(b1));
}

// ---------------------------------------------------------------------------
__global__ __launch_bounds__(256) void zero_s() {
  g_s[blockIdx.x * 256 + threadIdx.x] = 0.f;
}

// prep_w: conv_w [E][E][5] fp32 -> wt_h[e][k*512+ci] fp16
__global__ __launch_bounds__(256) void prep_w(const float* __restrict__ w) {
  int idx = blockIdx.x * 256 + threadIdx.x;       // e*2560 + (k*512+ci)
  int e = idx / 2560, kk = idx - e * 2560;
  int k = kk >> 9, ci = kk & 511;
  g_wt_h[idx] = __float2half_rn(w[e * 2560 + ci * 5 + k]);
}

// prep_x: x [B][E][L] fp32 -> xt_hi[b][t][ci] fp16 (transpose), half2 stores.
// Tile: 64 channels x 32 time. rows t in [NL, XL) zeroed.
__global__ __launch_bounds__(256) void prep_x(const float* __restrict__ x) {
  __shared__ float tile[64][33];
  int t0 = blockIdx.x * 32;
  int c0 = blockIdx.y * 64;
  int b  = blockIdx.z;
  int tx = threadIdx.x & 31, ty = threadIdx.x >> 5;   // ty 0..7
  #pragma unroll
  for (int j = 0; j < 8; ++j) {
    int row = ty + 8 * j;                 // channel within tile
    int t = t0 + tx;
    tile[row][tx] = (t < NL) ? x[((size_t)b * NE + c0 + row) * NL + t] : 0.f;
  }
  __syncthreads();
  #pragma unroll
  for (int j = 0; j < 4; ++j) {
    int tp = ty * 4 + j;                  // time within tile 0..31
    __half2 h2;
    h2.x = __float2half_rn(tile[2 * tx + 0][tp]);
    h2.y = __float2half_rn(tile[2 * tx + 1][tp]);
    *reinterpret_cast<__half2*>(
        &g_xt_hi[((size_t)b * XL + t0 + tp) * NE + c0 + 2 * tx]) = h2;
  }
}

// ---------------------------------------------------------------------------
// conv_mma: y[e,t] = bias[e] + sum_{k,ci} W[e,ci,k]*x[ci,t+k]
// CTA 128x256, 8 warps 2x4 (64x64 each), fp16 single-pass.
// 2-stage double buffer, K=128 per stage (two 64-halves). Score fused.
// ---------------------------------------------------------------------------
__device__ __forceinline__ void load_stage(int p, uint32_t sb, int tid,
                                           int e0, int b, int t0) {
  #pragma unroll
  for (int h = 0; h < 2; ++h) {
    int i  = 2 * p + h;                   // 64-chunk index 0..39
    int k  = i >> 3;
    int c0 = (i & 7) * 64;
    const __half* wh = g_wt_h  + (size_t)e0 * 2560 + k * 512 + c0;
    const __half* xh = g_xt_hi + ((size_t)b * XL + t0 + k) * NE + c0;
    uint32_t hb = sb + (uint32_t)h * HALF_BYTES;
    #pragma unroll
    for (int j = 0; j < 4; ++j) {                 // W: 128 rows x 8 chunks
      int q = tid + j * 256;
      int r = q >> 3, ch = q & 7;
      uint32_t d = swz((uint32_t)(r * 128 + ch * 16));
      cp16(hb + d, wh + (size_t)r * 2560 + ch * 8);
    }
    #pragma unroll
    for (int j = 0; j < 8; ++j) {                 // X: 256 rows x 8 chunks
      int q = tid + j * 256;
      int r = q >> 3, ch = q & 7;
      uint32_t d = swz((uint32_t)(r * 128 + ch * 16));
      cp16(hb + W_BYTES + d, xh + (size_t)r * NE + ch * 8);
    }
  }
  asm volatile("cp.async.commit_group;" ::: "memory");
}

__global__ __launch_bounds__(256, 1) void conv_mma(const float* __restrict__ bias,
                                                   const float* __restrict__ sw) {
  extern __shared__ char dsm[];
  uint32_t raw  = (uint32_t)__cvta_generic_to_shared(dsm);
  uint32_t base = (raw + 1023) & ~1023u;

  const int tid = threadIdx.x;
  const int mt = blockIdx.x & 3;
  const int tt = blockIdx.x >> 2;
  const int b  = blockIdx.y;
  const int e0 = mt * 128;
  const int t0 = tt * 256;

  const int l   = tid & 31;
  const int wrp = tid >> 5;
  const int m0w = (wrp >> 2) * 64;
  const int n0w = (wrp & 3) * 64;

  const int rA = (l & 15);
  const int cA = (l >> 4) * 16;
  const int rB = (l & 7) + ((l >> 4) & 1) * 8;
  const int cB = ((l >> 3) & 1) * 16;

  float acc[4][8][4];
  #pragma unroll
  for (int i = 0; i < 4; ++i)
    #pragma unroll
    for (int j = 0; j < 8; ++j)
      #pragma unroll
      for (int q = 0; q < 4; ++q) acc[i][j][q] = 0.f;

  load_stage(0, base + 1024, tid, e0, b, t0);

  for (int p = 0; p < PITERS; ++p) {
    asm volatile("cp.async.wait_group 0;" ::: "memory");
    __syncthreads();
    if (p + 1 < PITERS)
      load_stage(p + 1, base + 1024 + (uint32_t)((p + 1) & 1) * STAGE_BYTES,
                 tid, e0, b, t0);

    uint32_t sb = base + 1024 + (uint32_t)(p & 1) * STAGE_BYTES;
    #pragma unroll 1
    for (int h = 0; h < 2; ++h) {
      uint32_t sW = sb + (uint32_t)h * HALF_BYTES;
      uint32_t sX = sW + W_BYTES;
      #pragma unroll
      for (int ks = 0; ks < 4; ++ks) {
        const int kb = ks * 32;
        uint32_t a[4][4], bh[8][2];
        #pragma unroll
        for (int mi = 0; mi < 4; ++mi) {
          uint32_t off = swz((uint32_t)((m0w + mi * 16 + rA) * 128 + kb + cA));
          ldsm4(a[mi][0], a[mi][1], a[mi][2], a[mi][3], sW + off);
        }
        #pragma unroll
        for (int nj = 0; nj < 4; ++nj) {
          uint32_t off = swz((uint32_t)((n0w + nj * 16 + rB) * 128 + kb + cB));
          ldsm4(bh[nj * 2][0], bh[nj * 2][1], bh[nj * 2 + 1][0],
                bh[nj * 2 + 1][1], sX + off);
        }
        #pragma unroll
        for (int mi = 0; mi < 4; ++mi)
          #pragma unroll
          for (int ni = 0; ni < 8; ++ni)
            mma16816(acc[mi][ni], a[mi], bh[ni][0], bh[ni][1]);
      }
    }
  }

  // ---- epilogue: store y (+bias, zero tail) and fused score reduction ----
  float sacc[16];
  #pragma unroll
  for (int j = 0; j < 16; ++j) sacc[j] = 0.f;

  #pragma unroll
  for (int mi = 0; mi < 4; ++mi) {
    #pragma unroll
    for (int half = 0; half < 2; ++half) {
      int e = e0 + m0w + mi * 16 + (l >> 2) + half * 8;
      float bv = bias[e];
      float swv = __ldg(&sw[e]);
      float* yrow = g_y + ((size_t)(b * NE + e)) * NL;
      #pragma unroll
      for (int ni = 0; ni < 8; ++ni) {
        int t = t0 + n0w + ni * 8 + 2 * (l & 3);
        float2 v;
        if (t < NLC) {
          v.x = acc[mi][ni][half * 2 + 0] + bv;
          v.y = acc[mi][ni][half * 2 + 1] + bv;
        } else { v.x = 0.f; v.y = 0.f; }
        *reinterpret_cast<float2*>(yrow + t) = v;
        sacc[ni * 2 + 0] += swv * v.x;
        sacc[ni * 2 + 1] += swv * v.y;
      }
    }
  }
  // reduce over the 8 lane-groups sharing (l&3): strides 4, 8, 16
  #pragma unroll
  for (int st = 4; st <= 16; st <<= 1)
    #pragma unroll
    for (int j = 0; j < 16; ++j)
      sacc[j] += __shfl_xor_sync(0xFFFFFFFFu, sacc[j], st);

  if (l < 4) {
    float* srow = g_s + b * NL;
    #pragma unroll
    for (int j = 0; j < 16; ++j) {
      int t = t0 + n0w + (j >> 1) * 8 + 2 * l + (j & 1);
      atomicAdd(srow + t, sacc[j]);
    }
  }
}

// ---------------------------------------------------------------------------
// out: fused candidates + softmax over widths {1,2,3} + 2x avg-pool
// ---------------------------------------------------------------------------
__global__ __launch_bounds__(256) void out_kernel(float* __restrict__ out) {
  int idx = blockIdx.x * 256 + threadIdx.x;   // (b*NE+e)*4096 + to
  int to = idx & 4095;
  int be = idx >> 12;
  int b  = be >> 9;

  const float* y = g_y + (size_t)be * NL;
  const float* s = g_s + b * NL;

  int t0 = to * 2;
  float s0 = s[t0], s1 = s[t0 + 1];
  float y0 = y[t0], y1 = y[t0 + 1];
  float sc2 = 0.5f * (s0 + s1);
  float c2  = 0.5f * (y0 + y1);

  float r = 0.f;
  #pragma unroll
  for (int h = 0; h < 2; ++h) {
    int t = t0 + h;
    float sc1 = h ? s1 : s0;
    float c1  = h ? y1 : y0;
    float sc3, c3;
    if (t < 8190) {
      int bb = (t / 3) * 3;
      sc3 = (s[bb] + s[bb + 1] + s[bb + 2]) * (1.f / 3.f);
      c3  = (y[bb] + y[bb + 1] + y[bb + 2]) * (1.f / 3.f);
    } else { sc3 = 0.f; c3 = 0.f; }
    float m  = fmaxf(sc1, fmaxf(sc2, sc3));
    float e1 = __expf(sc1 - m);
    float e2 = __expf(sc2 - m);
    float e3 = __expf(sc3 - m);
    float inv = 1.f / (e1 + e2 + e3);
    r += (e1 * c1 + e2 * c2 + e3 * c3) * inv;
  }
  out[idx] = 0.5f * r;
}

// ---------------------------------------------------------------------------
extern "C" void kernel_launch(void* const* d_in, const int* in_sizes, int n_in,
                              void* d_out, int out_size) {
  const float* x  = (const float*)d_in[0];
  const float* cw = (const float*)d_in[1];
  const float* cb = (const float*)d_in[2];
  const float* sw = (const float*)d_in[3];
  float* out = (float*)d_out;

  cudaFuncSetAttribute(conv_mma, cudaFuncAttributeMaxDynamicSharedMemorySize, SMEM_SZ);

  zero_s<<<NB * NL / 256, 256>>>();
  prep_w<<<NE * NE * 5 / 256, 256>>>(cw);
  prep_x<<<dim3(XL / 32, NE / 64, NB), 256>>>(x);
  conv_mma<<<dim3(4 * (NL / 256), NB), 256, SMEM_SZ>>>(cb, sw);
  out_kernel<<<NB * NE * (NL / 2) / 256, 256>>>(out);
}

// round 17
// speedup vs baseline: 7.6365x; 1.0511x over previous
#include <cuda_runtime.h>
#include <cuda_fp16.h>
#include <cstdint>

#define NB  8
#define NE  512
#define NL  8192
#define NLC 8188
#define XL  8448            // NL + 256 pad rows (zeroed)

// ---- conv GEMM tiling: CTA 128 x 256, warp 64 x 64, fp16 single-pass ----
// Pipeline over 8 ci-chunks; each stage = W[5 taps][128r][128B] + X[260r][128B].
#define WT_BYTES 81920              // 5 * 128 * 128
#define XT_BYTES 33280              // 260 * 128
#define STAGE_BYTES (WT_BYTES + XT_BYTES)   // 115200
#define SMEM_SZ (1024 + 2 * STAGE_BYTES)    // 231424 <= 232448 max
#define PITERS 8                    // 512 ci / 64

// ---- scratch (__device__ globals; no runtime allocation) ----
__device__ __half g_xt_hi[(size_t)NB * XL * NE];
__device__ __half g_wt_h[NE * NE * 5];
__device__ float g_y[(size_t)NB * NE * NL];
__device__ float g_s[NB * NL];

// ---------------------------------------------------------------------------
__device__ __forceinline__ uint32_t swz(uint32_t o) { return o ^ ((o >> 3) & 0x70); }

__device__ __forceinline__ void cp16(uint32_t dst, const void* src) {
  asm volatile("cp.async.cg.shared.global [%0], [%1], 16;" :: "r"(dst), "l"(src));
}

__device__ __forceinline__ void ldsm4(uint32_t& r0, uint32_t& r1, uint32_t& r2,
                                      uint32_t& r3, uint32_t addr) {
  asm volatile("ldmatrix.sync.aligned.m8n8.x4.shared.b16 {%0,%1,%2,%3}, [%4];"
               : "=r"(r0), "=r"(r1), "=r"(r2), "=r"(r3) : "r"(addr));
}

__device__ __forceinline__ void mma16816(float* d, const uint32_t* a,
                                         uint32_t b0, uint32_t b1) {
  asm volatile(
    "mma.sync.aligned.m16n8k16.row.col.f32.f16.f16.f32 "
    "{%0,%1,%2,%3}, {%4,%5,%6,%7}, {%8,%9}, {%0,%1,%2,%3};"
    : "+f"(d[0]), "+f"(d[1]), "+f"(d[2]), "+f"(d[3])
    : "r"(a[0]), "r"(a[1]), "r"(a[2]), "r"(a[3]), "r"(b0), "r"(b1));
}

// ---------------------------------------------------------------------------
__global__ __launch_bounds__(256) void zero_s() {
  g_s[blockIdx.x * 256 + threadIdx.x] = 0.f;
}

// prep_w: conv_w [E][E][5] fp32 -> wt_h[e][k*512+ci] fp16
__global__ __launch_bounds__(256) void prep_w(const float* __restrict__ w) {
  int idx = blockIdx.x * 256 + threadIdx.x;       // e*2560 + (k*512+ci)
  int e = idx / 2560, kk = idx - e * 2560;
  int k = kk >> 9, ci = kk & 511;
  g_wt_h[idx] = __float2half_rn(w[e * 2560 + ci * 5 + k]);
}

// prep_x: x [B][E][L] fp32 -> xt_hi[b][t][ci] fp16 (transpose), half2 stores.
// Tile: 64 channels x 32 time. rows t in [NL, XL) zeroed.
__global__ __launch_bounds__(256) void prep_x(const float* __restrict__ x) {
  __shared__ float tile[64][33];
  int t0 = blockIdx.x * 32;
  int c0 = blockIdx.y * 64;
  int b  = blockIdx.z;
  int tx = threadIdx.x & 31, ty = threadIdx.x >> 5;   // ty 0..7
  #pragma unroll
  for (int j = 0; j < 8; ++j) {
    int row = ty + 8 * j;
    int t = t0 + tx;
    tile[row][tx] = (t < NL) ? x[((size_t)b * NE + c0 + row) * NL + t] : 0.f;
  }
  __syncthreads();
  #pragma unroll
  for (int j = 0; j < 4; ++j) {
    int tp = ty * 4 + j;
    __half2 h2;
    h2.x = __float2half_rn(tile[2 * tx + 0][tp]);
    h2.y = __float2half_rn(tile[2 * tx + 1][tp]);
    *reinterpret_cast<__half2*>(
        &g_xt_hi[((size_t)b * XL + t0 + tp) * NE + c0 + 2 * tx]) = h2;
  }
}

// ---------------------------------------------------------------------------
// conv_mma: y[e,t] = bias[e] + sum_{k,ci} W[e,ci,k]*x[ci,t+k]
// CTA 128x256, 8 warps 2x4 (64x64 each). Pipeline over 8 ci-chunks; per
// stage: W all 5 taps + one 260-row X tile shared by the taps (row offset k).
// ---------------------------------------------------------------------------
__device__ __forceinline__ void load_stage(int p, uint32_t sb, int tid,
                                           int e0, int b, int t0) {
  int c0 = p * 64;
  const __half* wh = g_wt_h  + (size_t)e0 * 2560 + c0;     // + r*2560 + tap*512
  const __half* xh = g_xt_hi + ((size_t)b * XL + t0) * NE + c0;
  // W: 5 taps x 128 rows x 8 chunks = 5120 cp16 ops
  #pragma unroll
  for (int j = 0; j < 20; ++j) {
    int q = tid + j * 256;
    int tap = q >> 10, rr = q & 1023;
    int r = rr >> 3, ch = rr & 7;
    uint32_t d = (uint32_t)(tap * 16384) + swz((uint32_t)(r * 128 + ch * 16));
    cp16(sb + d, wh + (size_t)r * 2560 + tap * 512 + ch * 8);
  }
  // X: 260 rows x 8 chunks = 2080 cp16 ops
  #pragma unroll
  for (int j = 0; j < 8; ++j) {
    int q = tid + j * 256;
    int r = q >> 3, ch = q & 7;
    uint32_t d = swz((uint32_t)(r * 128 + ch * 16));
    cp16(sb + WT_BYTES + d, xh + (size_t)r * NE + ch * 8);
  }
  if (tid < 32) {
    int q = 2048 + tid;
    int r = q >> 3, ch = q & 7;
    uint32_t d = swz((uint32_t)(r * 128 + ch * 16));
    cp16(sb + WT_BYTES + d, xh + (size_t)r * NE + ch * 8);
  }
  asm volatile("cp.async.commit_group;" ::: "memory");
}

__global__ __launch_bounds__(256, 1) void conv_mma(const float* __restrict__ bias,
                                                   const float* __restrict__ sw) {
  extern __shared__ char dsm[];
  uint32_t raw  = (uint32_t)__cvta_generic_to_shared(dsm);
  uint32_t base = (raw + 1023) & ~1023u;

  const int tid = threadIdx.x;
  const int mt = blockIdx.x & 3;
  const int tt = blockIdx.x >> 2;
  const int b  = blockIdx.y;
  const int e0 = mt * 128;
  const int t0 = tt * 256;

  const int l   = tid & 31;
  const int wrp = tid >> 5;
  const int m0w = (wrp >> 2) * 64;
  const int n0w = (wrp & 3) * 64;

  const int rA = (l & 15);
  const int cA = (l >> 4) * 16;
  const int rB = (l & 7) + ((l >> 4) & 1) * 8;
  const int cB = ((l >> 3) & 1) * 16;

  float acc[4][8][4];
  #pragma unroll
  for (int i = 0; i < 4; ++i)
    #pragma unroll
    for (int j = 0; j < 8; ++j)
      #pragma unroll
      for (int q = 0; q < 4; ++q) acc[i][j][q] = 0.f;

  load_stage(0, base + 1024, tid, e0, b, t0);

  for (int p = 0; p < PITERS; ++p) {
    asm volatile("cp.async.wait_group 0;" ::: "memory");
    __syncthreads();
    if (p + 1 < PITERS)
      load_stage(p + 1, base + 1024 + (uint32_t)((p + 1) & 1) * STAGE_BYTES,
                 tid, e0, b, t0);

    uint32_t sb = base + 1024 + (uint32_t)(p & 1) * STAGE_BYTES;
    uint32_t sX = sb + WT_BYTES;
    #pragma unroll 1
    for (int k = 0; k < 5; ++k) {
      uint32_t sWk = sb + (uint32_t)k * 16384;
      #pragma unroll
      for (int ks = 0; ks < 4; ++ks) {
        const int kb = ks * 32;
        uint32_t a[4][4], bh[8][2];
        #pragma unroll
        for (int mi = 0; mi < 4; ++mi) {
          uint32_t off = swz((uint32_t)((m0w + mi * 16 + rA) * 128 + kb + cA));
          ldsm4(a[mi][0], a[mi][1], a[mi][2], a[mi][3], sWk + off);
        }
        #pragma unroll
        for (int nj = 0; nj < 4; ++nj) {
          uint32_t off =
              swz((uint32_t)((n0w + nj * 16 + rB + k) * 128 + kb + cB));
          ldsm4(bh[nj * 2][0], bh[nj * 2][1], bh[nj * 2 + 1][0],
                bh[nj * 2 + 1][1], sX + off);
        }
        #pragma unroll
        for (int mi = 0; mi < 4; ++mi)
          #pragma unroll
          for (int ni = 0; ni < 8; ++ni)
            mma16816(acc[mi][ni], a[mi], bh[ni][0], bh[ni][1]);
      }
    }
  }

  // ---- epilogue: store y (+bias, zero tail) and fused score reduction ----
  float sacc[16];
  #pragma unroll
  for (int j = 0; j < 16; ++j) sacc[j] = 0.f;

  #pragma unroll
  for (int mi = 0; mi < 4; ++mi) {
    #pragma unroll
    for (int half = 0; half < 2; ++half) {
      int e = e0 + m0w + mi * 16 + (l >> 2) + half * 8;
      float bv = bias[e];
      float swv = __ldg(&sw[e]);
      float* yrow = g_y + ((size_t)(b * NE + e)) * NL;
      #pragma unroll
      for (int ni = 0; ni < 8; ++ni) {
        int t = t0 + n0w + ni * 8 + 2 * (l & 3);
        float2 v;
        if (t < NLC) {
          v.x = acc[mi][ni][half * 2 + 0] + bv;
          v.y = acc[mi][ni][half * 2 + 1] + bv;
        } else { v.x = 0.f; v.y = 0.f; }
        *reinterpret_cast<float2*>(yrow + t) = v;
        sacc[ni * 2 + 0] += swv * v.x;
        sacc[ni * 2 + 1] += swv * v.y;
      }
    }
  }
  // reduce over the 8 lane-groups sharing (l&3): strides 4, 8, 16
  #pragma unroll
  for (int st = 4; st <= 16; st <<= 1)
    #pragma unroll
    for (int j = 0; j < 16; ++j)
      sacc[j] += __shfl_xor_sync(0xFFFFFFFFu, sacc[j], st);

  if (l < 4) {
    float* srow = g_s + b * NL;
    #pragma unroll
    for (int j = 0; j < 16; ++j) {
      int t = t0 + n0w + (j >> 1) * 8 + 2 * l + (j & 1);
      atomicAdd(srow + t, sacc[j]);
    }
  }
}

// ---------------------------------------------------------------------------
// out: fused candidates + softmax over widths {1,2,3} + 2x avg-pool
// ---------------------------------------------------------------------------
__global__ __launch_bounds__(256) void out_kernel(float* __restrict__ out) {
  int idx = blockIdx.x * 256 + threadIdx.x;   // (b*NE+e)*4096 + to
  int to = idx & 4095;
  int be = idx >> 12;
  int b  = be >> 9;

  const float* y = g_y + (size_t)be * NL;
  const float* s = g_s + b * NL;

  int t0 = to * 2;
  float s0 = s[t0], s1 = s[t0 + 1];
  float y0 = y[t0], y1 = y[t0 + 1];
  float sc2 = 0.5f * (s0 + s1);
  float c2  = 0.5f * (y0 + y1);

  float r = 0.f;
  #pragma unroll
  for (int h = 0; h < 2; ++h) {
    int t = t0 + h;
    float sc1 = h ? s1 : s0;
    float c1  = h ? y1 : y0;
    float sc3, c3;
    if (t < 8190) {
      int bb = (t / 3) * 3;
      sc3 = (s[bb] + s[bb + 1] + s[bb + 2]) * (1.f / 3.f);
      c3  = (y[bb] + y[bb + 1] + y[bb + 2]) * (1.f / 3.f);
    } else { sc3 = 0.f; c3 = 0.f; }
    float m  = fmaxf(sc1, fmaxf(sc2, sc3));
    float e1 = __expf(sc1 - m);
    float e2 = __expf(sc2 - m);
    float e3 = __expf(sc3 - m);
    float inv = 1.f / (e1 + e2 + e3);
    r += (e1 * c1 + e2 * c2 + e3 * c3) * inv;
  }
  out[idx] = 0.5f * r;
}

// ---------------------------------------------------------------------------
extern "C" void kernel_launch(void* const* d_in, const int* in_sizes, int n_in,
                              void* d_out, int out_size) {
  const float* x  = (const float*)d_in[0];
  const float* cw = (const float*)d_in[1];
  const float* cb = (const float*)d_in[2];
  const float* sw = (const float*)d_in[3];
  float* out = (float*)d_out;

  cudaFuncSetAttribute(conv_mma, cudaFuncAttributeMaxDynamicSharedMemorySize, SMEM_SZ);

  zero_s<<<NB * NL / 256, 256>>>();
  prep_w<<<NE * NE * 5 / 256, 256>>>(cw);
  prep_x<<<dim3(NL / 32, NE / 64, NB), 256>>>(x);
  conv_mma<<<dim3(4 * (NL / 256), NB), 256, SMEM_SZ>>>(cb, sw);
  out_kernel<<<NB * NE * (NL / 2) / 256, 256>>>(out);
}